// round 14
// baseline (speedup 1.0000x reference)
#include <cuda_runtime.h>

#define N197   197
#define NN     38809        // 197*197
#define NNP    38812        // padded stride (float4-aligned)
#define NBATCH 32
#define NLAY   2            // processed layers: 4 and 11
#define KDISC  9702         // int(197*197*0.25)
#define PADR   256
#define PADC   208
#define NTF    1024

__device__ float    g_attn[NLAY * NBATCH * NNP];
__device__ float    g_norm[NLAY * NBATCH * PADR * PADC];   // zero-init; rows>=197 never written
__device__ unsigned g_hist[NLAY * NBATCH * 4096];          // zero-init; fused re-zeroes after use

// ---------------------------------------------------------------------------
// 1) mean over heads + round-0 histogram; 4 elements/thread (48 LDG in flight)
// ---------------------------------------------------------------------------
__global__ void __launch_bounds__(256) mean_kernel(const float* __restrict__ in) {
    const int lb = blockIdx.y;           // 0..63 = li*32 + b
    const int li = lb >> 5, b = lb & 31;
    const int layer = li ? 11 : 4;
    const float* __restrict__ base = in + ((long)(layer * NBATCH + b) * 12) * NN;
    const int lane = threadIdx.x & 31;
    unsigned* hb = &g_hist[lb * 4096];

    const int pb = blockIdx.x * 1024 + threadIdx.x;
    float s[4];
    bool v[4];
#pragma unroll
    for (int e = 0; e < 4; e++) {
        int p = pb + e * 256;
        v[e] = p < NN;
        s[e] = 0.f;
        if (v[e]) {
#pragma unroll
            for (int h = 0; h < 12; h++) s[e] += __ldcs(&base[(long)h * NN + p]);
        }
    }
#pragma unroll
    for (int e = 0; e < 4; e++) {
        int p = pb + e * 256;
        s[e] *= (1.0f / 12.0f);
        if (v[e]) g_attn[(long)lb * NNP + p] = s[e];
    }
#pragma unroll
    for (int e = 0; e < 4; e++) {
        unsigned key = __float_as_uint(s[e]) >> 20;
        unsigned m = __ballot_sync(0xffffffffu, v[e]);
        if (v[e]) {
            unsigned grp = __match_any_sync(m, key);
            if (lane == (int)__ffs(grp) - 1) atomicAdd(&hb[key], __popc(grp));
        }
    }
}

// ---------------------------------------------------------------------------
// block-wide "pick the bucket containing rank"
// ---------------------------------------------------------------------------
template<int PER>
__device__ __forceinline__ void block_pick(const unsigned* cnts, int nb, int rank,
                                           unsigned* wtot, int* s_out) {
    const int t = threadIdx.x, lane = t & 31, wid = t >> 5;
    const int base = t * PER;
    unsigned h[PER];
    unsigned sum = 0;
    if (base < nb) {
#pragma unroll
        for (int j = 0; j < PER; j++) { h[j] = cnts[base + j]; sum += h[j]; }
    }
    unsigned x = sum;
#pragma unroll
    for (int o = 1; o < 32; o <<= 1) {
        unsigned y = __shfl_up_sync(0xffffffffu, x, o);
        if (lane >= o) x += y;
    }
    if (lane == 31) wtot[wid] = x;
    __syncthreads();
    if (wid == 0) {
        unsigned y = wtot[lane];
#pragma unroll
        for (int o = 1; o < 32; o <<= 1) {
            unsigned z = __shfl_up_sync(0xffffffffu, y, o);
            if (lane >= o) y += z;
        }
        wtot[lane] = y;
    }
    __syncthreads();
    unsigned excl = x - sum + (wid ? wtot[wid - 1] : 0u);
    if (base < nb && (unsigned)rank >= excl && (unsigned)rank < excl + sum) {
        unsigned c = excl; int ch = base;
#pragma unroll
        for (int j = 0; j < PER; j++) {
            if (c + h[j] > (unsigned)rank) { ch = base + j; break; }
            c += h[j];
        }
        s_out[0] = ch; s_out[1] = rank - (int)c; s_out[2] = (int)c;
    }
    __syncthreads();
}

// ---------------------------------------------------------------------------
// 2) fused: pick0 -> reg-staged load + hist1 -> pick1 -> [rare round-2/ties]
//    -> single row sweep: discard + rowsum + normalized write (R11 exact)
// ---------------------------------------------------------------------------
__global__ void __launch_bounds__(NTF) fused_kernel() {
    extern __shared__ float sm[];          // NN floats
    __shared__ unsigned hist[4096];
    __shared__ unsigned wtot[32];
    __shared__ int s_pick[3];

    const int lb = blockIdx.x;
    const int t = threadIdx.x, lane = t & 31, wid = t >> 5;

    block_pick<4>(&g_hist[lb * 4096], 4096, KDISC - 1, wtot, s_pick);
    const int B1 = s_pick[0];
    int rank = s_pick[1];

    for (int i = t; i < 4096; i += NTF) { hist[i] = 0u; g_hist[lb * 4096 + i] = 0u; }
    __syncthreads();

    // ---- register-staged load (batches of 5 float4, MLP=5/thread) + hist1 ----
    const float* src = g_attn + (long)lb * NNP;
    const float4* s4 = (const float4*)src;
    float4* d4 = (float4*)sm;
    const int N4 = NN / 4;                 // 9702
    {
        float4 v[5];
#pragma unroll
        for (int k = 0; k < 5; k++) v[k] = s4[k * NTF + t];      // max 5119 < 9702
#pragma unroll
        for (int k = 0; k < 5; k++) {
            int i = k * NTF + t;
            d4[i] = v[k];
            const float vv[4] = {v[k].x, v[k].y, v[k].z, v[k].w};
#pragma unroll
            for (int j = 0; j < 4; j++) {
                unsigned key = __float_as_uint(vv[j]);
                if ((int)(key >> 20) == B1) atomicAdd(&hist[(key >> 8) & 0xFFFu], 1u);
            }
        }
        bool ok[5];
#pragma unroll
        for (int k = 0; k < 5; k++) {
            int i = (k + 5) * NTF + t;
            ok[k] = i < N4;
            v[k] = ok[k] ? s4[i] : make_float4(0.f, 0.f, 0.f, 0.f);
        }
#pragma unroll
        for (int k = 0; k < 5; k++) {
            if (ok[k]) {
                int i = (k + 5) * NTF + t;
                d4[i] = v[k];
                const float vv[4] = {v[k].x, v[k].y, v[k].z, v[k].w};
#pragma unroll
                for (int j = 0; j < 4; j++) {
                    unsigned key = __float_as_uint(vv[j]);
                    if ((int)(key >> 20) == B1) atomicAdd(&hist[(key >> 8) & 0xFFFu], 1u);
                }
            }
        }
    }
    if (t == 0) {                          // tail element 38808
        float v = src[NN - 1]; sm[NN - 1] = v;
        unsigned key = __float_as_uint(v);
        if ((int)(key >> 20) == B1) atomicAdd(&hist[(key >> 8) & 0xFFFu], 1u);
    }
    __syncthreads();

    block_pick<4>(hist, 4096, rank, wtot, s_pick);
    const int B2 = s_pick[0];
    rank = s_pick[1];
    const unsigned K24 = ((unsigned)B1 << 12) | (unsigned)B2;
    const unsigned ties2 = hist[B2];

    int mode;           // 0: zero key24<=K24 | 1: zero key<=T | 2: zero key<T (ties pre-zeroed)
    unsigned T = 0;
    if (ties2 == 1u) {
        mode = 0;
    } else {
        for (int i = t; i < 256; i += NTF) hist[i] = 0u;
        __syncthreads();
        const int IT = (NN + NTF - 1) / NTF;   // 38
        for (int k = 0; k < IT; k++) {
            int i = k * NTF + t;
            if (i < NN) {
                unsigned key = __float_as_uint(sm[i]);
                if ((key >> 8) == K24) atomicAdd(&hist[key & 0xFFu], 1u);
            }
        }
        __syncthreads();
        block_pick<1>(hist, 256, rank, wtot, s_pick);
        const int B3 = s_pick[0];
        const int rank3 = s_pick[1];
        T = (K24 << 8) | (unsigned)B3;
        const unsigned ties3 = hist[B3];
        const int need = rank3 + 1;
        if ((unsigned)need == ties3) {
            mode = 1;
        } else {
            mode = 2;
            const int SEG = (NN + NTF - 1) / NTF;
            int start = t * SEG, end = min(start + SEG, NN);
            int cnt = 0;
            for (int i = start; i < end; i++)
                if (__float_as_uint(sm[i]) == T) cnt++;
            int x = cnt;
#pragma unroll
            for (int o = 1; o < 32; o <<= 1) {
                int y = __shfl_up_sync(0xffffffffu, x, o);
                if (lane >= o) x += y;
            }
            if (lane == 31) wtot[wid] = (unsigned)x;
            __syncthreads();
            if (wid == 0) {
                unsigned y = wtot[lane];
#pragma unroll
                for (int o = 1; o < 32; o <<= 1) {
                    unsigned z = __shfl_up_sync(0xffffffffu, y, o);
                    if (lane >= o) y += z;
                }
                wtot[lane] = y;
            }
            __syncthreads();
            int pre = x - cnt + (wid ? (int)wtot[wid - 1] : 0);
            for (int i = start; i < end; i++) {
                if (__float_as_uint(sm[i]) == T) {
                    if (pre < need && i != 0) sm[i] = 0.f;
                    pre++;
                }
            }
            __syncthreads();
        }
    }

    // ---- single sweep: discard + row sum + normalized write (warp per row) ----
    for (int r = wid; r < N197; r += 32) {
        const int rowbase = r * N197;
        float s = 0.f;
        for (int c = lane; c < N197; c += 32) {
            int i = rowbase + c;
            float v = sm[i];
            unsigned key = __float_as_uint(v);
            bool z = (mode == 0) ? ((key >> 8) <= K24)
                   : (mode == 1) ? (key <= T)
                                 : (key < T);
            if (z && i != 0) { sm[i] = 0.f; v = 0.f; }
            s += v;
        }
#pragma unroll
        for (int o = 16; o; o >>= 1) s += __shfl_xor_sync(0xffffffffu, s, o);
        const float inv = 1.0f / (s + 1.0f);   // the *0.5 cancels: (x+d)/(sum+1)

        float4* orow = (float4*)(g_norm + (long)lb * (PADR * PADC) + r * PADC);
        for (int v4 = lane; v4 < PADC / 4; v4 += 32) {   // 52 float4 per row
            int c0 = v4 * 4;
            float4 val;
            val.x = (c0     < N197) ? (sm[rowbase + c0    ] + (r == c0     ? 1.f : 0.f)) * inv : 0.f;
            val.y = (c0 + 1 < N197) ? (sm[rowbase + c0 + 1] + (r == c0 + 1 ? 1.f : 0.f)) * inv : 0.f;
            val.z = (c0 + 2 < N197) ? (sm[rowbase + c0 + 2] + (r == c0 + 2 ? 1.f : 0.f)) * inv : 0.f;
            val.w = (c0 + 3 < N197) ? (sm[rowbase + c0 + 3] + (r == c0 + 3 ? 1.f : 0.f)) * inv : 0.f;
            orow[v4] = val;
        }
    }
}

// ---------------------------------------------------------------------------
// 3) out[b] = A11[b] @ A4[b] via mma.sync m16n8k8 tf32.
//    128x128 tile, 8 warps (2/SMSP), warp tile 64x32 (4x4 mma tiles).
// ---------------------------------------------------------------------------
__device__ __forceinline__ unsigned to_tf32(float x) {
    unsigned u;
    asm("cvt.rna.tf32.f32 %0, %1;" : "=r"(u) : "f"(x));
    return u;
}

#define GBK 32
__global__ void __launch_bounds__(256) gemm_kernel(float* __restrict__ Cout) {
    __shared__ unsigned As[128][GBK + 1];   // tf32 bits, [m][k]
    __shared__ unsigned Bs[GBK][128 + 1];   // tf32 bits, [k][n]

    const int t = threadIdx.x, lane = t & 31, wid = t >> 5;
    const int b = blockIdx.z;
    const int row0 = blockIdx.y * 128, col0 = blockIdx.x * 128;
    const float* __restrict__ Ag = g_norm + (long)(NBATCH + b) * (PADR * PADC); // layer 11 [m][k]
    const float* __restrict__ Bg = g_norm + (long)b * (PADR * PADC);            // layer 4  [k][n]
    float* C = Cout + (long)b * NN;

    const int g  = lane >> 2;          // groupID (0..7)
    const int tg = lane & 3;           // threadID_in_group (0..3)
    const int wm = (wid & 1) * 64;     // warp m-offset (2 rows of warps)
    const int wn = (wid >> 1) * 32;    // warp n-offset (4 cols of warps)

    float acc[4][4][4];
#pragma unroll
    for (int mt = 0; mt < 4; mt++)
#pragma unroll
        for (int nt = 0; nt < 4; nt++)
#pragma unroll
            for (int j = 0; j < 4; j++) acc[mt][nt][j] = 0.f;

    for (int kc = 0; kc < 7; kc++) {
        const int k0 = kc * GBK;
        // A tile: 128 rows x 32 k (1024 float4 / 256 threads = 4 each)
#pragma unroll
        for (int l = 0; l < 4; l++) {
            int idx = l * 256 + t;
            int r = idx >> 3, q = idx & 7;
            float4 v = make_float4(0.f, 0.f, 0.f, 0.f);
            if (k0 + q * 4 < PADC)
                v = *(const float4*)&Ag[(row0 + r) * PADC + k0 + q * 4];
            As[r][q * 4 + 0] = to_tf32(v.x);
            As[r][q * 4 + 1] = to_tf32(v.y);
            As[r][q * 4 + 2] = to_tf32(v.z);
            As[r][q * 4 + 3] = to_tf32(v.w);
        }
        // B tile: 32 k-rows x 128 n (1024 float4 / 256 threads = 4 each)
        // cols >= PADC within a row read in-slot garbage that only feeds
        // never-stored output columns; k-rows are guarded (zero pad).
#pragma unroll
        for (int l = 0; l < 4; l++) {
            int idx = l * 256 + t;
            int kk = idx >> 5, nq = idx & 31;
            float4 v = make_float4(0.f, 0.f, 0.f, 0.f);
            if (k0 + kk < PADC)
                v = *(const float4*)&Bg[(k0 + kk) * PADC + col0 + nq * 4];
            Bs[kk][nq * 4 + 0] = to_tf32(v.x);
            Bs[kk][nq * 4 + 1] = to_tf32(v.y);
            Bs[kk][nq * 4 + 2] = to_tf32(v.z);
            Bs[kk][nq * 4 + 3] = to_tf32(v.w);
        }
        __syncthreads();

        const int nks = (kc == 6) ? 2 : 4;     // chunk 6: k 192..207 only
        for (int ks = 0; ks < nks; ks++) {
            const int kb = ks * 8;
            unsigned af[4][4], bf[4][2];
#pragma unroll
            for (int mt = 0; mt < 4; mt++) {
                int m = wm + mt * 16;
                af[mt][0] = As[m + g    ][kb + tg    ];
                af[mt][1] = As[m + g + 8][kb + tg    ];
                af[mt][2] = As[m + g    ][kb + tg + 4];
                af[mt][3] = As[m + g + 8][kb + tg + 4];
            }
#pragma unroll
            for (int nt = 0; nt < 4; nt++) {
                int n = wn + nt * 8 + g;
                bf[nt][0] = Bs[kb + tg    ][n];
                bf[nt][1] = Bs[kb + tg + 4][n];
            }
#pragma unroll
            for (int mt = 0; mt < 4; mt++)
#pragma unroll
                for (int nt = 0; nt < 4; nt++) {
                    asm volatile(
                        "mma.sync.aligned.m16n8k8.row.col.f32.tf32.tf32.f32 "
                        "{%0,%1,%2,%3}, {%4,%5,%6,%7}, {%8,%9}, {%0,%1,%2,%3};"
                        : "+f"(acc[mt][nt][0]), "+f"(acc[mt][nt][1]),
                          "+f"(acc[mt][nt][2]), "+f"(acc[mt][nt][3])
                        : "r"(af[mt][0]), "r"(af[mt][1]), "r"(af[mt][2]), "r"(af[mt][3]),
                          "r"(bf[nt][0]), "r"(bf[nt][1]));
                }
        }
        __syncthreads();
    }

    // epilogue: c0,c1 at (row g, cols 2tg,2tg+1); c2,c3 at row g+8
#pragma unroll
    for (int mt = 0; mt < 4; mt++) {
#pragma unroll
        for (int nt = 0; nt < 4; nt++) {
            int gr = row0 + wm + mt * 16 + g;
            int gc = col0 + wn + nt * 8 + tg * 2;
            if (gr < N197) {
                if (gc     < N197) C[gr * N197 + gc    ] = acc[mt][nt][0];
                if (gc + 1 < N197) C[gr * N197 + gc + 1] = acc[mt][nt][1];
            }
            if (gr + 8 < N197) {
                if (gc     < N197) C[(gr + 8) * N197 + gc    ] = acc[mt][nt][2];
                if (gc + 1 < N197) C[(gr + 8) * N197 + gc + 1] = acc[mt][nt][3];
            }
        }
    }
}

// ---------------------------------------------------------------------------
extern "C" void kernel_launch(void* const* d_in, const int* in_sizes, int n_in,
                              void* d_out, int out_size) {
    const float* attn = (const float*)d_in[0];  // (12,32,12,197,197) fp32
    float* out = (float*)d_out;                 // (32,197,197) fp32
    (void)in_sizes; (void)n_in; (void)out_size;

    cudaFuncSetAttribute(fused_kernel, cudaFuncAttributeMaxDynamicSharedMemorySize,
                         NN * (int)sizeof(float));

    dim3 gm(38, NLAY * NBATCH);     // 38*1024 = 38912 elems, 4 per thread
    mean_kernel<<<gm, 256>>>(attn);
    fused_kernel<<<NLAY * NBATCH, NTF, NN * sizeof(float)>>>();
    dim3 gg(2, 2, NBATCH);          // 2 N-tiles x 2 M-tiles x 32 batches
    gemm_kernel<<<gg, 256>>>(out);
}

// round 15
// speedup vs baseline: 1.0672x; 1.0672x over previous
#include <cuda_runtime.h>

#define N197   197
#define NN     38809        // 197*197
#define NNP    38812        // padded stride (float4-aligned)
#define NBATCH 32
#define NLAY   2            // processed layers: 4 and 11
#define KDISC  9702         // int(197*197*0.25)
#define PADR   256
#define PADC   208
#define NTF    1024

__device__ float    g_attn[NLAY * NBATCH * NNP];
__device__ float    g_norm[NLAY * NBATCH * PADR * PADC];   // zero-init; rows>=197 never written
__device__ unsigned g_hist[NLAY * NBATCH * 4096];          // zero-init; fused re-zeroes after use

// ---------------------------------------------------------------------------
// 1) mean over heads + round-0 histogram (exact R13 form — measured 23.7us)
// ---------------------------------------------------------------------------
__global__ void __launch_bounds__(256) mean_kernel(const float* __restrict__ in) {
    const int lb = blockIdx.y;           // 0..63 = li*32 + b
    const int li = lb >> 5, b = lb & 31;
    const int layer = li ? 11 : 4;
    const float* __restrict__ base = in + ((long)(layer * NBATCH + b) * 12) * NN;
    const int lane = threadIdx.x & 31;

    const int p0 = blockIdx.x * 512 + threadIdx.x;
    const int p1 = p0 + 256;
    const bool v0 = p0 < NN, v1 = p1 < NN;
    float s0 = 0.f, s1 = 0.f;
    if (v0) {
#pragma unroll
        for (int h = 0; h < 12; h++) s0 += __ldcs(&base[(long)h * NN + p0]);
    }
    if (v1) {
#pragma unroll
        for (int h = 0; h < 12; h++) s1 += __ldcs(&base[(long)h * NN + p1]);
    }
    s0 *= (1.0f / 12.0f);
    s1 *= (1.0f / 12.0f);
    if (v0) g_attn[(long)lb * NNP + p0] = s0;
    if (v1) g_attn[(long)lb * NNP + p1] = s1;

    unsigned* hb = &g_hist[lb * 4096];
    {
        unsigned key = __float_as_uint(s0) >> 20;
        unsigned m = __ballot_sync(0xffffffffu, v0);
        if (v0) {
            unsigned grp = __match_any_sync(m, key);
            if (lane == (int)__ffs(grp) - 1) atomicAdd(&hb[key], __popc(grp));
        }
    }
    {
        unsigned key = __float_as_uint(s1) >> 20;
        unsigned m = __ballot_sync(0xffffffffu, v1);
        if (v1) {
            unsigned grp = __match_any_sync(m, key);
            if (lane == (int)__ffs(grp) - 1) atomicAdd(&hb[key], __popc(grp));
        }
    }
}

// ---------------------------------------------------------------------------
// block-wide "pick the bucket containing rank"
// ---------------------------------------------------------------------------
template<int PER>
__device__ __forceinline__ void block_pick(const unsigned* cnts, int nb, int rank,
                                           unsigned* wtot, int* s_out) {
    const int t = threadIdx.x, lane = t & 31, wid = t >> 5;
    const int base = t * PER;
    unsigned h[PER];
    unsigned sum = 0;
    if (base < nb) {
#pragma unroll
        for (int j = 0; j < PER; j++) { h[j] = cnts[base + j]; sum += h[j]; }
    }
    unsigned x = sum;
#pragma unroll
    for (int o = 1; o < 32; o <<= 1) {
        unsigned y = __shfl_up_sync(0xffffffffu, x, o);
        if (lane >= o) x += y;
    }
    if (lane == 31) wtot[wid] = x;
    __syncthreads();
    if (wid == 0) {
        unsigned y = wtot[lane];
#pragma unroll
        for (int o = 1; o < 32; o <<= 1) {
            unsigned z = __shfl_up_sync(0xffffffffu, y, o);
            if (lane >= o) y += z;
        }
        wtot[lane] = y;
    }
    __syncthreads();
    unsigned excl = x - sum + (wid ? wtot[wid - 1] : 0u);
    if (base < nb && (unsigned)rank >= excl && (unsigned)rank < excl + sum) {
        unsigned c = excl; int ch = base;
#pragma unroll
        for (int j = 0; j < PER; j++) {
            if (c + h[j] > (unsigned)rank) { ch = base + j; break; }
            c += h[j];
        }
        s_out[0] = ch; s_out[1] = rank - (int)c; s_out[2] = (int)c;
    }
    __syncthreads();
}

// ---------------------------------------------------------------------------
// 2) fused: pick0 -> reg-staged load + hist1 -> pick1 -> [rare round-2/ties]
//    -> single row sweep: discard + rowsum + normalized write (R11 exact)
// ---------------------------------------------------------------------------
__global__ void __launch_bounds__(NTF) fused_kernel() {
    extern __shared__ float sm[];          // NN floats
    __shared__ unsigned hist[4096];
    __shared__ unsigned wtot[32];
    __shared__ int s_pick[3];

    const int lb = blockIdx.x;
    const int t = threadIdx.x, lane = t & 31, wid = t >> 5;

    block_pick<4>(&g_hist[lb * 4096], 4096, KDISC - 1, wtot, s_pick);
    const int B1 = s_pick[0];
    int rank = s_pick[1];

    for (int i = t; i < 4096; i += NTF) { hist[i] = 0u; g_hist[lb * 4096 + i] = 0u; }
    __syncthreads();

    // ---- register-staged load (batches of 5 float4, MLP=5/thread) + hist1 ----
    const float* src = g_attn + (long)lb * NNP;
    const float4* s4 = (const float4*)src;
    float4* d4 = (float4*)sm;
    const int N4 = NN / 4;                 // 9702
    {
        float4 v[5];
#pragma unroll
        for (int k = 0; k < 5; k++) v[k] = s4[k * NTF + t];      // max 5119 < 9702
#pragma unroll
        for (int k = 0; k < 5; k++) {
            int i = k * NTF + t;
            d4[i] = v[k];
            const float vv[4] = {v[k].x, v[k].y, v[k].z, v[k].w};
#pragma unroll
            for (int j = 0; j < 4; j++) {
                unsigned key = __float_as_uint(vv[j]);
                if ((int)(key >> 20) == B1) atomicAdd(&hist[(key >> 8) & 0xFFFu], 1u);
            }
        }
        bool ok[5];
#pragma unroll
        for (int k = 0; k < 5; k++) {
            int i = (k + 5) * NTF + t;
            ok[k] = i < N4;
            v[k] = ok[k] ? s4[i] : make_float4(0.f, 0.f, 0.f, 0.f);
        }
#pragma unroll
        for (int k = 0; k < 5; k++) {
            if (ok[k]) {
                int i = (k + 5) * NTF + t;
                d4[i] = v[k];
                const float vv[4] = {v[k].x, v[k].y, v[k].z, v[k].w};
#pragma unroll
                for (int j = 0; j < 4; j++) {
                    unsigned key = __float_as_uint(vv[j]);
                    if ((int)(key >> 20) == B1) atomicAdd(&hist[(key >> 8) & 0xFFFu], 1u);
                }
            }
        }
    }
    if (t == 0) {                          // tail element 38808
        float v = src[NN - 1]; sm[NN - 1] = v;
        unsigned key = __float_as_uint(v);
        if ((int)(key >> 20) == B1) atomicAdd(&hist[(key >> 8) & 0xFFFu], 1u);
    }
    __syncthreads();

    block_pick<4>(hist, 4096, rank, wtot, s_pick);
    const int B2 = s_pick[0];
    rank = s_pick[1];
    const unsigned K24 = ((unsigned)B1 << 12) | (unsigned)B2;
    const unsigned ties2 = hist[B2];

    int mode;           // 0: zero key24<=K24 | 1: zero key<=T | 2: zero key<T (ties pre-zeroed)
    unsigned T = 0;
    if (ties2 == 1u) {
        mode = 0;
    } else {
        for (int i = t; i < 256; i += NTF) hist[i] = 0u;
        __syncthreads();
        const int IT = (NN + NTF - 1) / NTF;   // 38
        for (int k = 0; k < IT; k++) {
            int i = k * NTF + t;
            if (i < NN) {
                unsigned key = __float_as_uint(sm[i]);
                if ((key >> 8) == K24) atomicAdd(&hist[key & 0xFFu], 1u);
            }
        }
        __syncthreads();
        block_pick<1>(hist, 256, rank, wtot, s_pick);
        const int B3 = s_pick[0];
        const int rank3 = s_pick[1];
        T = (K24 << 8) | (unsigned)B3;
        const unsigned ties3 = hist[B3];
        const int need = rank3 + 1;
        if ((unsigned)need == ties3) {
            mode = 1;
        } else {
            mode = 2;
            const int SEG = (NN + NTF - 1) / NTF;
            int start = t * SEG, end = min(start + SEG, NN);
            int cnt = 0;
            for (int i = start; i < end; i++)
                if (__float_as_uint(sm[i]) == T) cnt++;
            int x = cnt;
#pragma unroll
            for (int o = 1; o < 32; o <<= 1) {
                int y = __shfl_up_sync(0xffffffffu, x, o);
                if (lane >= o) x += y;
            }
            if (lane == 31) wtot[wid] = (unsigned)x;
            __syncthreads();
            if (wid == 0) {
                unsigned y = wtot[lane];
#pragma unroll
                for (int o = 1; o < 32; o <<= 1) {
                    unsigned z = __shfl_up_sync(0xffffffffu, y, o);
                    if (lane >= o) y += z;
                }
                wtot[lane] = y;
            }
            __syncthreads();
            int pre = x - cnt + (wid ? (int)wtot[wid - 1] : 0);
            for (int i = start; i < end; i++) {
                if (__float_as_uint(sm[i]) == T) {
                    if (pre < need && i != 0) sm[i] = 0.f;
                    pre++;
                }
            }
            __syncthreads();
        }
    }

    // ---- single sweep: discard + row sum + normalized write (warp per row) ----
    for (int r = wid; r < N197; r += 32) {
        const int rowbase = r * N197;
        float s = 0.f;
        for (int c = lane; c < N197; c += 32) {
            int i = rowbase + c;
            float v = sm[i];
            unsigned key = __float_as_uint(v);
            bool z = (mode == 0) ? ((key >> 8) <= K24)
                   : (mode == 1) ? (key <= T)
                                 : (key < T);
            if (z && i != 0) { sm[i] = 0.f; v = 0.f; }
            s += v;
        }
#pragma unroll
        for (int o = 16; o; o >>= 1) s += __shfl_xor_sync(0xffffffffu, s, o);
        const float inv = 1.0f / (s + 1.0f);   // the *0.5 cancels: (x+d)/(sum+1)

        float4* orow = (float4*)(g_norm + (long)lb * (PADR * PADC) + r * PADC);
        for (int v4 = lane; v4 < PADC / 4; v4 += 32) {   // 52 float4 per row
            int c0 = v4 * 4;
            float4 val;
            val.x = (c0     < N197) ? (sm[rowbase + c0    ] + (r == c0     ? 1.f : 0.f)) * inv : 0.f;
            val.y = (c0 + 1 < N197) ? (sm[rowbase + c0 + 1] + (r == c0 + 1 ? 1.f : 0.f)) * inv : 0.f;
            val.z = (c0 + 2 < N197) ? (sm[rowbase + c0 + 2] + (r == c0 + 2 ? 1.f : 0.f)) * inv : 0.f;
            val.w = (c0 + 3 < N197) ? (sm[rowbase + c0 + 3] + (r == c0 + 3 ? 1.f : 0.f)) * inv : 0.f;
            orow[v4] = val;
        }
    }
}

// ---------------------------------------------------------------------------
// 3) out[b] = A11[b] @ A4[b] via mma.sync m16n8k8 tf32.
//    128x128 tile, 8 warps (2/SMSP), warp tile 64x32, register prefetch.
// ---------------------------------------------------------------------------
__device__ __forceinline__ unsigned to_tf32(float x) {
    unsigned u;
    asm("cvt.rna.tf32.f32 %0, %1;" : "=r"(u) : "f"(x));
    return u;
}

#define GBK 32
__global__ void __launch_bounds__(256) gemm_kernel(float* __restrict__ Cout) {
    __shared__ unsigned As[128][GBK + 1];   // tf32 bits, [m][k]
    __shared__ unsigned Bs[GBK][128 + 1];   // tf32 bits, [k][n]

    const int t = threadIdx.x, lane = t & 31, wid = t >> 5;
    const int b = blockIdx.z;
    const int row0 = blockIdx.y * 128, col0 = blockIdx.x * 128;
    const float* __restrict__ Ag = g_norm + (long)(NBATCH + b) * (PADR * PADC); // layer 11 [m][k]
    const float* __restrict__ Bg = g_norm + (long)b * (PADR * PADC);            // layer 4  [k][n]
    float* C = Cout + (long)b * NN;

    const int g  = lane >> 2;          // groupID (0..7)
    const int tg = lane & 3;           // threadID_in_group (0..3)
    const int wm = (wid & 1) * 64;     // warp m-offset (2 rows of warps)
    const int wn = (wid >> 1) * 32;    // warp n-offset (4 cols of warps)

    // loader indices (4 A-float4 and 4 B-float4 per thread per chunk)
    const int lar = t >> 1, laq = (t & 1) * 4;         // A: rows via idx=l*256+t -> r=idx>>3
    (void)lar; (void)laq;

    float acc[4][4][4];
#pragma unroll
    for (int mt = 0; mt < 4; mt++)
#pragma unroll
        for (int nt = 0; nt < 4; nt++)
#pragma unroll
            for (int j = 0; j < 4; j++) acc[mt][nt][j] = 0.f;

    float4 pva[4], pvb[4];
    // prefetch chunk 0
#pragma unroll
    for (int l = 0; l < 4; l++) {
        int idx = l * 256 + t;
        int r = idx >> 3, q = idx & 7;
        pva[l] = make_float4(0.f, 0.f, 0.f, 0.f);
        if (q * 4 < PADC) pva[l] = *(const float4*)&Ag[(row0 + r) * PADC + q * 4];
        int kk = idx >> 5, nq = idx & 31;
        pvb[l] = make_float4(0.f, 0.f, 0.f, 0.f);
        if (kk < PADC) pvb[l] = *(const float4*)&Bg[kk * PADC + col0 + nq * 4];
    }

    for (int kc = 0; kc < 7; kc++) {
        // store prefetched chunk to smem (tf32 convert)
#pragma unroll
        for (int l = 0; l < 4; l++) {
            int idx = l * 256 + t;
            int r = idx >> 3, q = idx & 7;
            As[r][q * 4 + 0] = to_tf32(pva[l].x);
            As[r][q * 4 + 1] = to_tf32(pva[l].y);
            As[r][q * 4 + 2] = to_tf32(pva[l].z);
            As[r][q * 4 + 3] = to_tf32(pva[l].w);
            int kk = idx >> 5, nq = idx & 31;
            Bs[kk][nq * 4 + 0] = to_tf32(pvb[l].x);
            Bs[kk][nq * 4 + 1] = to_tf32(pvb[l].y);
            Bs[kk][nq * 4 + 2] = to_tf32(pvb[l].z);
            Bs[kk][nq * 4 + 3] = to_tf32(pvb[l].w);
        }
        __syncthreads();

        // prefetch next chunk from L2 while computing this one
        if (kc + 1 < 7) {
            const int k0 = (kc + 1) * GBK;
#pragma unroll
            for (int l = 0; l < 4; l++) {
                int idx = l * 256 + t;
                int r = idx >> 3, q = idx & 7;
                pva[l] = make_float4(0.f, 0.f, 0.f, 0.f);
                if (k0 + q * 4 < PADC)
                    pva[l] = *(const float4*)&Ag[(row0 + r) * PADC + k0 + q * 4];
                int kk = idx >> 5, nq = idx & 31;
                pvb[l] = make_float4(0.f, 0.f, 0.f, 0.f);
                if (k0 + kk < PADC)
                    pvb[l] = *(const float4*)&Bg[(k0 + kk) * PADC + col0 + nq * 4];
            }
        }

        const int nks = (kc == 6) ? 2 : 4;     // chunk 6: k 192..207 only
        for (int ks = 0; ks < nks; ks++) {
            const int kb = ks * 8;
            unsigned af[4][4], bf[4][2];
#pragma unroll
            for (int mt = 0; mt < 4; mt++) {
                int m = wm + mt * 16;
                af[mt][0] = As[m + g    ][kb + tg    ];
                af[mt][1] = As[m + g + 8][kb + tg    ];
                af[mt][2] = As[m + g    ][kb + tg + 4];
                af[mt][3] = As[m + g + 8][kb + tg + 4];
            }
#pragma unroll
            for (int nt = 0; nt < 4; nt++) {
                int n = wn + nt * 8 + g;
                bf[nt][0] = Bs[kb + tg    ][n];
                bf[nt][1] = Bs[kb + tg + 4][n];
            }
#pragma unroll
            for (int mt = 0; mt < 4; mt++)
#pragma unroll
                for (int nt = 0; nt < 4; nt++) {
                    asm volatile(
                        "mma.sync.aligned.m16n8k8.row.col.f32.tf32.tf32.f32 "
                        "{%0,%1,%2,%3}, {%4,%5,%6,%7}, {%8,%9}, {%0,%1,%2,%3};"
                        : "+f"(acc[mt][nt][0]), "+f"(acc[mt][nt][1]),
                          "+f"(acc[mt][nt][2]), "+f"(acc[mt][nt][3])
                        : "r"(af[mt][0]), "r"(af[mt][1]), "r"(af[mt][2]), "r"(af[mt][3]),
                          "r"(bf[nt][0]), "r"(bf[nt][1]));
                }
        }
        __syncthreads();
    }

    // epilogue: c0,c1 at (row g, cols 2tg,2tg+1); c2,c3 at row g+8
#pragma unroll
    for (int mt = 0; mt < 4; mt++) {
#pragma unroll
        for (int nt = 0; nt < 4; nt++) {
            int gr = row0 + wm + mt * 16 + g;
            int gc = col0 + wn + nt * 8 + tg * 2;
            if (gr < N197) {
                if (gc     < N197) C[gr * N197 + gc    ] = acc[mt][nt][0];
                if (gc + 1 < N197) C[gr * N197 + gc + 1] = acc[mt][nt][1];
            }
            if (gr + 8 < N197) {
                if (gc     < N197) C[(gr + 8) * N197 + gc    ] = acc[mt][nt][2];
                if (gc + 1 < N197) C[(gr + 8) * N197 + gc + 1] = acc[mt][nt][3];
            }
        }
    }
}

// ---------------------------------------------------------------------------
extern "C" void kernel_launch(void* const* d_in, const int* in_sizes, int n_in,
                              void* d_out, int out_size) {
    const float* attn = (const float*)d_in[0];  // (12,32,12,197,197) fp32
    float* out = (float*)d_out;                 // (32,197,197) fp32
    (void)in_sizes; (void)n_in; (void)out_size;

    cudaFuncSetAttribute(fused_kernel, cudaFuncAttributeMaxDynamicSharedMemorySize,
                         NN * (int)sizeof(float));

    dim3 gm(76, NLAY * NBATCH);     // 76*512 = 38912 elems, 2 per thread
    mean_kernel<<<gm, 256>>>(attn);
    fused_kernel<<<NLAY * NBATCH, NTF, NN * sizeof(float)>>>();
    dim3 gg(2, 2, NBATCH);          // 2 N-tiles x 2 M-tiles x 32 batches
    gemm_kernel<<<gg, 256>>>(out);
}